// round 5
// baseline (speedup 1.0000x reference)
#include <cuda_runtime.h>
#include <cuda_bf16.h>
#include <cstdint>

// Problem constants
constexpr int CB = 4;      // batch
constexpr int CN = 2048;   // query seq
constexpr int CM = 2048;   // context seq
constexpr int CC = 1024;   // channels
constexpr int CH = 16;     // heads
constexpr int CD = 64;     // head dim

// Scratch (device globals: allocation-free rule)
__device__ float g_q[(size_t)CB * CN * CC];          // 32 MB
__device__ float g_kv[(size_t)CB * CM * 2 * CC];     // 64 MB
__device__ float g_attn[(size_t)CB * CN * CC];       // 32 MB

// ============================================================================
// mma.sync m16n8k16 bf16 -> f32 (available on base sm_100 target)
// ============================================================================
__device__ __forceinline__ void mma16816(float* d,
    uint32_t a0, uint32_t a1, uint32_t a2, uint32_t a3,
    uint32_t b0, uint32_t b1)
{
    asm volatile(
        "mma.sync.aligned.m16n8k16.row.col.f32.bf16.bf16.f32 "
        "{%0,%1,%2,%3}, {%4,%5,%6,%7}, {%8,%9}, {%0,%1,%2,%3};"
        : "+f"(d[0]), "+f"(d[1]), "+f"(d[2]), "+f"(d[3])
        : "r"(a0), "r"(a1), "r"(a2), "r"(a3), "r"(b0), "r"(b1));
}

// convert 8 consecutive floats -> packed hi/lo bf16 (uint4 each)
__device__ __forceinline__ void cvt8_split(const float* g, uint4& hi, uint4& lo) {
    float f[8];
    float4 a = *(const float4*)g;
    float4 b = *(const float4*)(g + 4);
    f[0]=a.x; f[1]=a.y; f[2]=a.z; f[3]=a.w;
    f[4]=b.x; f[5]=b.y; f[6]=b.z; f[7]=b.w;
    union { __nv_bfloat162 h2[4]; uint4 u; } Uh, Ul;
#pragma unroll
    for (int j = 0; j < 4; j++) {
        __nv_bfloat16 h0 = __float2bfloat16(f[2*j]);
        __nv_bfloat16 h1 = __float2bfloat16(f[2*j+1]);
        __nv_bfloat16 l0 = __float2bfloat16(f[2*j]   - __bfloat162float(h0));
        __nv_bfloat16 l1 = __float2bfloat16(f[2*j+1] - __bfloat162float(h1));
        Uh.h2[j] = __halves2bfloat162(h0, h1);
        Ul.h2[j] = __halves2bfloat162(l0, l1);
    }
    hi = Uh.u; lo = Ul.u;
}

// ============================================================================
// NT GEMM via mma.sync with bf16-split (3-term) fp32 emulation.
// C[M,N] = A[M,K] * B[N,K]^T (+ optional bias[n]).
// CTA tile 128x128, BK=32, 256 threads (8 warps, 4x2 grid, 32x64 per warp).
// smem rows padded to 20 b32 (80B): conflict-free fragment loads + 16B stores.
// Requires M%128==0, N%128==0, K%32==0.
// ============================================================================
constexpr int GS = 20;               // b32 stride per smem row
constexpr int GT_ROWS = 128;         // rows per tile
constexpr int GT_TSZ = GT_ROWS * GS; // b32 per tile (2560)

__global__ void __launch_bounds__(256) gemm_mma_kernel(
    const float* __restrict__ A, const float* __restrict__ Bm,
    float* __restrict__ C, int M, int N, int K, const float* __restrict__ bias)
{
    __shared__ uint32_t sm[4 * GT_TSZ];   // Ahi, Alo, Bhi, Blo  (40 KB)
    uint32_t* sAhi = sm;
    uint32_t* sAlo = sm + GT_TSZ;
    uint32_t* sBhi = sm + 2 * GT_TSZ;
    uint32_t* sBlo = sm + 3 * GT_TSZ;

    const int tid = threadIdx.x;
    const int wid = tid >> 5;
    const int lane = tid & 31;
    const int warp_m = wid & 3;          // 4 warps over 128 rows
    const int warp_n = wid >> 2;         // 2 warps over 128 cols
    const int m0 = blockIdx.y * 128;
    const int n0 = blockIdx.x * 128;

    float acc[2][8][4];
#pragma unroll
    for (int i = 0; i < 2; i++)
#pragma unroll
        for (int j = 0; j < 8; j++)
#pragma unroll
            for (int q = 0; q < 4; q++) acc[i][j][q] = 0.f;

    const int lr = tid >> 1;          // load row 0..127
    const int lh = tid & 1;           // half: cols 0-15 or 16-31

    for (int k0 = 0; k0 < K; k0 += 32) {
        // ---- load + split-convert A and B tiles (128 x 32 fp32 each) ----
        {
            const float* ap = A + (size_t)(m0 + lr) * K + k0 + lh * 16;
            uint4 h0, l0, h1, l1;
            cvt8_split(ap, h0, l0);
            cvt8_split(ap + 8, h1, l1);
            int o = lr * GS + lh * 8;
            *(uint4*)(sAhi + o)     = h0;  *(uint4*)(sAhi + o + 4) = h1;
            *(uint4*)(sAlo + o)     = l0;  *(uint4*)(sAlo + o + 4) = l1;
            const float* bp = Bm + (size_t)(n0 + lr) * K + k0 + lh * 16;
            cvt8_split(bp, h0, l0);
            cvt8_split(bp + 8, h1, l1);
            *(uint4*)(sBhi + o)     = h0;  *(uint4*)(sBhi + o + 4) = h1;
            *(uint4*)(sBlo + o)     = l0;  *(uint4*)(sBlo + o + 4) = l1;
        }
        __syncthreads();

        // ---- 3 terms: hi*hi, hi*lo, lo*hi ----
#pragma unroll
        for (int t = 0; t < 3; t++) {
            const uint32_t* As = (t < 2) ? sAhi : sAlo;
            const uint32_t* Bs = (t == 1) ? sBlo : sBhi;
#pragma unroll
            for (int ks = 0; ks < 2; ks++) {
                const int ac = (lane & 3) + ks * 8;
                const int ar = warp_m * 32 + (lane >> 2);
                uint32_t a[2][4];
#pragma unroll
                for (int i = 0; i < 2; i++) {
                    int r = ar + i * 16;
                    a[i][0] = As[r * GS + ac];
                    a[i][1] = As[(r + 8) * GS + ac];
                    a[i][2] = As[r * GS + ac + 4];
                    a[i][3] = As[(r + 8) * GS + ac + 4];
                }
#pragma unroll
                for (int j = 0; j < 8; j++) {
                    int br = warp_n * 64 + j * 8 + (lane >> 2);
                    uint32_t b0 = Bs[br * GS + ac];
                    uint32_t b1 = Bs[br * GS + ac + 4];
                    mma16816(acc[0][j], a[0][0], a[0][1], a[0][2], a[0][3], b0, b1);
                    mma16816(acc[1][j], a[1][0], a[1][1], a[1][2], a[1][3], b0, b1);
                }
            }
        }
        __syncthreads();
    }

    // ---- epilogue ----
#pragma unroll
    for (int i = 0; i < 2; i++) {
        int row = m0 + warp_m * 32 + i * 16 + (lane >> 2);
#pragma unroll
        for (int j = 0; j < 8; j++) {
            int col = n0 + warp_n * 64 + j * 8 + (lane & 3) * 2;
            float2 w0, w1;
            w0.x = acc[i][j][0]; w0.y = acc[i][j][1];
            w1.x = acc[i][j][2]; w1.y = acc[i][j][3];
            if (bias) {
                float2 bb = *(const float2*)(bias + col);
                w0.x += bb.x; w0.y += bb.y;
                w1.x += bb.x; w1.y += bb.y;
            }
            *(float2*)(C + (size_t)row * N + col) = w0;
            *(float2*)(C + (size_t)(row + 8) * N + col) = w1;
        }
    }
}

// ----------------------------------------------------------------------------
// RoPE (in place). Applies to the first 1024 columns of each row.
// ----------------------------------------------------------------------------
__global__ void rope_kernel(float* __restrict__ x, const float* __restrict__ fc,
                            int rows, int rowstride)
{
    int id = blockIdx.x * blockDim.x + threadIdx.x;
    if (id >= rows * 512) return;
    int row = id >> 9;
    int w   = id & 511;
    int n   = row & (CN - 1);
    float* p = x + (size_t)row * rowstride + w * 2;
    float2 v = *(float2*)p;
    float2 f = *(const float2*)(fc + n * 64 + (w & 31) * 2);
    float2 r;
    r.x = v.x * f.x - v.y * f.y;
    r.y = v.y * f.x + v.x * f.y;
    *(float2*)p = r;
}

// ----------------------------------------------------------------------------
// Flash attention, fp32, online softmax (unchanged — known good).
// ----------------------------------------------------------------------------
constexpr int FS_Q = 64 * 65;
constexpr int FS_K = 64 * 65;
constexpr int FS_V = 64 * 68;
constexpr int FLASH_SMEM = (FS_Q + FS_K + FS_V + 192) * 4;

__global__ void __launch_bounds__(256) flash_kernel(
    const float* __restrict__ q, const float* __restrict__ kv,
    float* __restrict__ outp)
{
    extern __shared__ float sm[];
    float (*Qs)[65]  = (float(*)[65])sm;
    float (*KPs)[65] = (float(*)[65])(sm + FS_Q);
    float (*Vs)[68]  = (float(*)[68])(sm + FS_Q + FS_K);
    float* mrow = sm + FS_Q + FS_K + FS_V;
    float* lrow = mrow + 64;
    float* arow = lrow + 64;

    const int tid = threadIdx.x;
    const int tx = tid & 15, ty = tid >> 4;
    const int nt = blockIdx.x, h = blockIdx.y, b = blockIdx.z;

    const float* qbase = q  + (size_t)(b * CN + nt * 64) * CC + h * CD;
    const float* kvb   = kv + (size_t)b * CM * (2 * CC) + h * CD;

#pragma unroll
    for (int l = 0; l < 4; l++) {
        int idx = tid + l * 256;
        int r  = idx >> 4;
        int dc = (idx & 15) << 2;
        float4 v = *(const float4*)(qbase + (size_t)r * CC + dc);
        Qs[r][dc + 0] = v.x * 0.125f; Qs[r][dc + 1] = v.y * 0.125f;
        Qs[r][dc + 2] = v.z * 0.125f; Qs[r][dc + 3] = v.w * 0.125f;
    }
    if (tid < 64) { mrow[tid] = -1e30f; lrow[tid] = 0.f; }

    float oacc[4][4];
#pragma unroll
    for (int i = 0; i < 4; i++)
#pragma unroll
        for (int j = 0; j < 4; j++) oacc[i][j] = 0.f;

    __syncthreads();

    for (int jt = 0; jt < CM / 64; jt++) {
#pragma unroll
        for (int l = 0; l < 4; l++) {
            int idx = tid + l * 256;
            int r  = idx >> 4;
            int dc = (idx & 15) << 2;
            const float* p = kvb + (size_t)(jt * 64 + r) * (2 * CC) + dc;
            float4 kk = *(const float4*)p;
            KPs[r][dc + 0] = kk.x; KPs[r][dc + 1] = kk.y;
            KPs[r][dc + 2] = kk.z; KPs[r][dc + 3] = kk.w;
            float4 vv = *(const float4*)(p + CC);
            Vs[r][dc + 0] = vv.x; Vs[r][dc + 1] = vv.y;
            Vs[r][dc + 2] = vv.z; Vs[r][dc + 3] = vv.w;
        }
        __syncthreads();

        float s[4][4];
#pragma unroll
        for (int i = 0; i < 4; i++)
#pragma unroll
            for (int j = 0; j < 4; j++) s[i][j] = 0.f;
#pragma unroll
        for (int d = 0; d < 64; d++) {
            float a[4], bb[4];
#pragma unroll
            for (int i = 0; i < 4; i++) a[i] = Qs[ty * 4 + i][d];
#pragma unroll
            for (int j = 0; j < 4; j++) bb[j] = KPs[tx * 4 + j][d];
#pragma unroll
            for (int i = 0; i < 4; i++)
#pragma unroll
                for (int j = 0; j < 4; j++)
                    s[i][j] += a[i] * bb[j];
        }
        __syncthreads();

#pragma unroll
        for (int i = 0; i < 4; i++)
#pragma unroll
            for (int j = 0; j < 4; j++)
                KPs[ty * 4 + i][tx * 4 + j] = s[i][j];
        __syncthreads();

        {
            int r  = tid >> 2;
            int c0 = (tid & 3) << 4;
            float mx = -1e30f;
#pragma unroll
            for (int c = 0; c < 16; c++) mx = fmaxf(mx, KPs[r][c0 + c]);
            mx = fmaxf(mx, __shfl_xor_sync(0xffffffffu, mx, 1));
            mx = fmaxf(mx, __shfl_xor_sync(0xffffffffu, mx, 2));
            float mold = mrow[r];
            float mnew = fmaxf(mold, mx);
            float ps = 0.f;
#pragma unroll
            for (int c = 0; c < 16; c++) {
                float pv = __expf(KPs[r][c0 + c] - mnew);
                KPs[r][c0 + c] = pv;
                ps += pv;
            }
            ps += __shfl_xor_sync(0xffffffffu, ps, 1);
            ps += __shfl_xor_sync(0xffffffffu, ps, 2);
            if ((tid & 3) == 0) {
                float al = __expf(mold - mnew);
                arow[r] = al;
                lrow[r] = lrow[r] * al + ps;
                mrow[r] = mnew;
            }
        }
        __syncthreads();

#pragma unroll
        for (int i = 0; i < 4; i++) {
            float al = arow[ty * 4 + i];
#pragma unroll
            for (int j = 0; j < 4; j++) oacc[i][j] *= al;
        }
#pragma unroll
        for (int mm = 0; mm < 64; mm++) {
            float a[4];
#pragma unroll
            for (int i = 0; i < 4; i++) a[i] = KPs[ty * 4 + i][mm];
            float4 bb = *(float4*)&Vs[mm][tx * 4];
#pragma unroll
            for (int i = 0; i < 4; i++) {
                oacc[i][0] += a[i] * bb.x;
                oacc[i][1] += a[i] * bb.y;
                oacc[i][2] += a[i] * bb.z;
                oacc[i][3] += a[i] * bb.w;
            }
        }
        __syncthreads();
    }

    float* obase = outp + (size_t)(b * CN + nt * 64) * CC + h * CD;
#pragma unroll
    for (int i = 0; i < 4; i++) {
        float inv = 1.f / lrow[ty * 4 + i];
        float4 w4;
        w4.x = oacc[i][0] * inv; w4.y = oacc[i][1] * inv;
        w4.z = oacc[i][2] * inv; w4.w = oacc[i][3] * inv;
        *(float4*)(obase + (size_t)(ty * 4 + i) * CC + tx * 4) = w4;
    }
}

// ----------------------------------------------------------------------------
// Launch
// ----------------------------------------------------------------------------
extern "C" void kernel_launch(void* const* d_in, const int* in_sizes, int n_in,
                              void* d_out, int out_size)
{
    const float* x     = (const float*)d_in[0];
    const float* ctx   = (const float*)d_in[1];
    const float* fc    = (const float*)d_in[2];
    const float* Wq    = (const float*)d_in[3];
    const float* Wkv   = (const float*)d_in[4];
    const float* Wproj = (const float*)d_in[5];
    const float* bproj = (const float*)d_in[6];
    float* out = (float*)d_out;

    float *q, *kvp, *attn;
    cudaGetSymbolAddress((void**)&q,    g_q);
    cudaGetSymbolAddress((void**)&kvp,  g_kv);
    cudaGetSymbolAddress((void**)&attn, g_attn);

    cudaFuncSetAttribute(flash_kernel,
                         cudaFuncAttributeMaxDynamicSharedMemorySize, 64 * 1024);

    // 1) q = x @ Wq^T          (8192 x 1024 x 1024)
    gemm_mma_kernel<<<dim3(CC / 128, (CB * CN) / 128), 256>>>(
        x, Wq, q, CB * CN, CC, CC, nullptr);

    // 2) kv = context @ Wkv^T  (8192 x 2048 x 1024)
    gemm_mma_kernel<<<dim3((2 * CC) / 128, (CB * CM) / 128), 256>>>(
        ctx, Wkv, kvp, CB * CM, 2 * CC, CC, nullptr);

    // 3) RoPE on q and on k half of kv
    {
        int tq = CB * CN * 512;
        rope_kernel<<<(tq + 255) / 256, 256>>>(q, fc, CB * CN, CC);
        int tk = CB * CM * 512;
        rope_kernel<<<(tk + 255) / 256, 256>>>(kvp, fc, CB * CM, 2 * CC);
    }

    // 4) attention
    flash_kernel<<<dim3(CN / 64, CH, CB), 256, FLASH_SMEM>>>(q, kvp, attn);

    // 5) out = attn @ Wproj^T + bproj
    gemm_mma_kernel<<<dim3(CC / 128, (CB * CN) / 128), 256>>>(
        attn, Wproj, out, CB * CN, CC, CC, bproj);
}

// round 8
// speedup vs baseline: 1.8329x; 1.8329x over previous
#include <cuda_runtime.h>
#include <cuda_bf16.h>
#include <cstdint>

// Problem constants
constexpr int CB = 4;      // batch
constexpr int CN = 2048;   // query seq
constexpr int CM = 2048;   // context seq
constexpr int CC = 1024;   // channels
constexpr int CH = 16;     // heads
constexpr int CD = 64;     // head dim

// Scratch (device globals: allocation-free rule)
__device__ float g_q[(size_t)CB * CN * CC];          // 32 MB
__device__ float g_kv[(size_t)CB * CM * 2 * CC];     // 64 MB
__device__ float g_attn[(size_t)CB * CN * CC];       // 32 MB

// bf16-split K / V (V transposed): 16 MB each
constexpr size_t KV_U4 = (size_t)CB * CH * CM * CD / 8;   // uint4 count
__device__ uint4 g_khi[KV_U4];
__device__ uint4 g_klo[KV_U4];
__device__ uint4 g_vhi[KV_U4];   // layout [b][h][d][m]
__device__ uint4 g_vlo[KV_U4];

// ============================================================================
// mma.sync m16n8k16 bf16 -> f32
// ============================================================================
__device__ __forceinline__ void mma16816(float* d,
    uint32_t a0, uint32_t a1, uint32_t a2, uint32_t a3,
    uint32_t b0, uint32_t b1)
{
    asm volatile(
        "mma.sync.aligned.m16n8k16.row.col.f32.bf16.bf16.f32 "
        "{%0,%1,%2,%3}, {%4,%5,%6,%7}, {%8,%9}, {%0,%1,%2,%3};"
        : "+f"(d[0]), "+f"(d[1]), "+f"(d[2]), "+f"(d[3])
        : "r"(a0), "r"(a1), "r"(a2), "r"(a3), "r"(b0), "r"(b1));
}

// split 2 floats into packed hi / lo bf16 words
__device__ __forceinline__ void split2(float x, float y, uint32_t& h, uint32_t& l) {
    __nv_bfloat16 hx = __float2bfloat16(x);
    __nv_bfloat16 hy = __float2bfloat16(y);
    float rx = x - __bfloat162float(hx);
    float ry = y - __bfloat162float(hy);
    __nv_bfloat162 th = __halves2bfloat162(hx, hy);
    __nv_bfloat162 tl = __halves2bfloat162(__float2bfloat16(rx), __float2bfloat16(ry));
    h = *(uint32_t*)&th;
    l = *(uint32_t*)&tl;
}

// convert 8 consecutive floats -> packed hi/lo bf16 (uint4 each)
__device__ __forceinline__ void cvt8_split(const float* g, uint4& hi, uint4& lo) {
    float f[8];
    float4 a = *(const float4*)g;
    float4 b = *(const float4*)(g + 4);
    f[0]=a.x; f[1]=a.y; f[2]=a.z; f[3]=a.w;
    f[4]=b.x; f[5]=b.y; f[6]=b.z; f[7]=b.w;
    uint32_t* ph = (uint32_t*)&hi;
    uint32_t* pl = (uint32_t*)&lo;
#pragma unroll
    for (int j = 0; j < 4; j++) split2(f[2*j], f[2*j+1], ph[j], pl[j]);
}

__device__ __forceinline__ uint32_t smem_u32(const void* p) {
    uint32_t a;
    asm("{ .reg .u64 t; cvta.to.shared.u64 t, %1; cvt.u32.u64 %0, t; }"
        : "=r"(a) : "l"(p));
    return a;
}
__device__ __forceinline__ void cp_async16(uint32_t dst, const void* src) {
    asm volatile("cp.async.cg.shared.global [%0], [%1], 16;"
                 :: "r"(dst), "l"(src) : "memory");
}
__device__ __forceinline__ void cp_commit() {
    asm volatile("cp.async.commit_group;" ::: "memory");
}
__device__ __forceinline__ void cp_wait1() {
    asm volatile("cp.async.wait_group 1;" ::: "memory");
}

// ============================================================================
// NT GEMM via mma.sync with bf16-split (3-term) fp32 emulation (unchanged).
// ============================================================================
constexpr int GS = 20;
constexpr int GT_TSZ = 128 * GS;

__global__ void __launch_bounds__(256) gemm_mma_kernel(
    const float* __restrict__ A, const float* __restrict__ Bm,
    float* __restrict__ C, int M, int N, int K, const float* __restrict__ bias)
{
    __shared__ uint32_t sm[4 * GT_TSZ];
    uint32_t* sAhi = sm;
    uint32_t* sAlo = sm + GT_TSZ;
    uint32_t* sBhi = sm + 2 * GT_TSZ;
    uint32_t* sBlo = sm + 3 * GT_TSZ;

    const int tid = threadIdx.x;
    const int wid = tid >> 5;
    const int lane = tid & 31;
    const int warp_m = wid & 3;
    const int warp_n = wid >> 2;
    const int m0 = blockIdx.y * 128;
    const int n0 = blockIdx.x * 128;

    float acc[2][8][4];
#pragma unroll
    for (int i = 0; i < 2; i++)
#pragma unroll
        for (int j = 0; j < 8; j++)
#pragma unroll
            for (int q = 0; q < 4; q++) acc[i][j][q] = 0.f;

    const int lr = tid >> 1;
    const int lh = tid & 1;

    for (int k0 = 0; k0 < K; k0 += 32) {
        {
            const float* ap = A + (size_t)(m0 + lr) * K + k0 + lh * 16;
            uint4 h0, l0, h1, l1;
            cvt8_split(ap, h0, l0);
            cvt8_split(ap + 8, h1, l1);
            int o = lr * GS + lh * 8;
            *(uint4*)(sAhi + o)     = h0;  *(uint4*)(sAhi + o + 4) = h1;
            *(uint4*)(sAlo + o)     = l0;  *(uint4*)(sAlo + o + 4) = l1;
            const float* bp = Bm + (size_t)(n0 + lr) * K + k0 + lh * 16;
            cvt8_split(bp, h0, l0);
            cvt8_split(bp + 8, h1, l1);
            *(uint4*)(sBhi + o)     = h0;  *(uint4*)(sBhi + o + 4) = h1;
            *(uint4*)(sBlo + o)     = l0;  *(uint4*)(sBlo + o + 4) = l1;
        }
        __syncthreads();

#pragma unroll
        for (int t = 0; t < 3; t++) {
            const uint32_t* As = (t < 2) ? sAhi : sAlo;
            const uint32_t* Bs = (t == 1) ? sBlo : sBhi;
#pragma unroll
            for (int ks = 0; ks < 2; ks++) {
                const int ac = (lane & 3) + ks * 8;
                const int ar = warp_m * 32 + (lane >> 2);
                uint32_t a[2][4];
#pragma unroll
                for (int i = 0; i < 2; i++) {
                    int r = ar + i * 16;
                    a[i][0] = As[r * GS + ac];
                    a[i][1] = As[(r + 8) * GS + ac];
                    a[i][2] = As[r * GS + ac + 4];
                    a[i][3] = As[(r + 8) * GS + ac + 4];
                }
#pragma unroll
                for (int j = 0; j < 8; j++) {
                    int br = warp_n * 64 + j * 8 + (lane >> 2);
                    uint32_t b0 = Bs[br * GS + ac];
                    uint32_t b1 = Bs[br * GS + ac + 4];
                    mma16816(acc[0][j], a[0][0], a[0][1], a[0][2], a[0][3], b0, b1);
                    mma16816(acc[1][j], a[1][0], a[1][1], a[1][2], a[1][3], b0, b1);
                }
            }
        }
        __syncthreads();
    }

#pragma unroll
    for (int i = 0; i < 2; i++) {
        int row = m0 + warp_m * 32 + i * 16 + (lane >> 2);
#pragma unroll
        for (int j = 0; j < 8; j++) {
            int col = n0 + warp_n * 64 + j * 8 + (lane & 3) * 2;
            float2 w0, w1;
            w0.x = acc[i][j][0]; w0.y = acc[i][j][1];
            w1.x = acc[i][j][2]; w1.y = acc[i][j][3];
            if (bias) {
                float2 bb = *(const float2*)(bias + col);
                w0.x += bb.x; w0.y += bb.y;
                w1.x += bb.x; w1.y += bb.y;
            }
            *(float2*)(C + (size_t)row * N + col) = w0;
            *(float2*)(C + (size_t)(row + 8) * N + col) = w1;
        }
    }
}

// ----------------------------------------------------------------------------
// RoPE (in place) for Q only.
// ----------------------------------------------------------------------------
__global__ void rope_kernel(float* __restrict__ x, const float* __restrict__ fc,
                            int rows, int rowstride)
{
    int id = blockIdx.x * blockDim.x + threadIdx.x;
    if (id >= rows * 512) return;
    int row = id >> 9;
    int w   = id & 511;
    int n   = row & (CN - 1);
    float* p = x + (size_t)row * rowstride + w * 2;
    float2 v = *(float2*)p;
    float2 f = *(const float2*)(fc + n * 64 + (w & 31) * 2);
    float2 r;
    r.x = v.x * f.x - v.y * f.y;
    r.y = v.y * f.x + v.x * f.y;
    *(float2*)p = r;
}

// ----------------------------------------------------------------------------
// Convert pre-pass: K-RoPE + bf16 split; V split + transpose.
// Grid: (M/64, H, B), 256 threads. Each CTA: 64 keys x 64 dims of one (b,h).
// sv stride 68 floats (272B): every row float4-aligned.
// ----------------------------------------------------------------------------
__global__ void __launch_bounds__(256) conv_kernel(const float* __restrict__ fc)
{
    __shared__ float sv[64][68];
    const int tid = threadIdx.x;
    const int blk = blockIdx.x, h = blockIdx.y, b = blockIdx.z;
    const int bh = b * CH + h;

    const int kl = tid >> 2;          // key 0..63
    const int ch = tid & 3;           // 16-elem chunk
    const int m  = blk * 64 + kl;
    const int d0 = ch * 16;

    // ---- K: read, rope, split, store [b][h][m][d] ----
    {
        const float* kp = g_kv + ((size_t)b * CM + m) * (2 * CC) + h * CD + d0;
        float v[16];
        *(float4*)(v + 0)  = *(const float4*)(kp + 0);
        *(float4*)(v + 4)  = *(const float4*)(kp + 4);
        *(float4*)(v + 8)  = *(const float4*)(kp + 8);
        *(float4*)(v + 12) = *(const float4*)(kp + 12);
        uint4 hi[2], lo[2];
        uint32_t* ph = (uint32_t*)hi;
        uint32_t* pl = (uint32_t*)lo;
#pragma unroll
        for (int i = 0; i < 8; i++) {
            int d2 = ch * 8 + i;
            float2 f = *(const float2*)(fc + m * 64 + d2 * 2);
            float rx = v[2*i] * f.x - v[2*i+1] * f.y;
            float ry = v[2*i+1] * f.x + v[2*i] * f.y;
            split2(rx, ry, ph[i], pl[i]);
        }
        size_t o = (((size_t)bh * CM + m) * CD + d0) / 8;
        g_khi[o] = hi[0]; g_khi[o + 1] = hi[1];
        g_klo[o] = lo[0]; g_klo[o + 1] = lo[1];
    }

    // ---- V: stage to smem, transpose, split, store [b][h][d][m] ----
    {
        const float* vp = g_kv + ((size_t)b * CM + m) * (2 * CC) + CC + h * CD + d0;
        float4 a = *(const float4*)(vp + 0);
        float4 c = *(const float4*)(vp + 4);
        float4 e = *(const float4*)(vp + 8);
        float4 g = *(const float4*)(vp + 12);
        *(float4*)&sv[kl][d0 + 0]  = a;
        *(float4*)&sv[kl][d0 + 4]  = c;
        *(float4*)&sv[kl][d0 + 8]  = e;
        *(float4*)&sv[kl][d0 + 12] = g;
    }
    __syncthreads();
    {
        const int d  = tid >> 2;      // 0..63
        const int kc = tid & 3;       // key chunk
        uint4 hi[2], lo[2];
        uint32_t* ph = (uint32_t*)hi;
        uint32_t* pl = (uint32_t*)lo;
#pragma unroll
        for (int i = 0; i < 8; i++) {
            int key = kc * 16 + 2 * i;
            split2(sv[key][d], sv[key + 1][d], ph[i], pl[i]);
        }
        size_t o = (((size_t)bh * CD + d) * CM + blk * 64 + kc * 16) / 8;
        g_vhi[o] = hi[0]; g_vhi[o + 1] = hi[1];
        g_vlo[o] = lo[0]; g_vlo[o + 1] = lo[1];
    }
}

// ----------------------------------------------------------------------------
// Tensor-core flash attention.
// Grid (CN/128, CH, CB), 256 threads (8 warps x 16 q-rows).
// K/V bf16-split tiles stream via cp.async, double buffered.
// smem tile: 64 rows x 36 b32 (pad). Tiles: khi, klo, vhi, vlo.
// Each tile = 64 rows x 32 words -> 512 16B-chunks; 256 threads x 2 halves.
// ----------------------------------------------------------------------------
constexpr int FT = 64 * 36;              // b32 per tile
constexpr int FBUF = 4 * FT;             // b32 per buffer (9216)
constexpr int FLASH_SMEM = 2 * FBUF * 4; // 73728 bytes

__global__ void __launch_bounds__(256) flash_mma_kernel(
    const float* __restrict__ q, float* __restrict__ outp)
{
    extern __shared__ uint32_t fsm[];
    const int tid  = threadIdx.x;
    const int wid  = tid >> 5;
    const int lane = tid & 31;
    const int gid  = lane >> 2;     // row-in-frag
    const int tig  = lane & 3;
    const int nt = blockIdx.x, h = blockIdx.y, b = blockIdx.z;
    const int bh = b * CH + h;

    const uint32_t smb = smem_u32(fsm);

    // ---- issue cp.async for block jt into buffer buf (full tiles) ----
    const int lrow8 = tid >> 3;     // 0..31
    const int lc8   = tid & 7;      // word chunk 0..7 (4 words = 16B each)
    auto issue = [&](int jt, int buf) {
#pragma unroll
        for (int half = 0; half < 2; half++) {
            int row = lrow8 + half * 32;
            uint32_t so = smb + buf * (FBUF * 4) + (row * 36 + lc8 * 4) * 4;
            size_t kof = (((size_t)bh * CM + jt * 64 + row) * CD + lc8 * 8) * 2;
            size_t vof = (((size_t)bh * CD + row) * CM + jt * 64 + lc8 * 8) * 2;
            cp_async16(so,               (const char*)g_khi + kof);
            cp_async16(so + FT * 4,     (const char*)g_klo + kof);
            cp_async16(so + 2 * FT * 4, (const char*)g_vhi + vof);
            cp_async16(so + 3 * FT * 4, (const char*)g_vlo + vof);
        }
    };

    issue(0, 0);
    cp_commit();

    // ---- load Q fragments (scaled by 0.125 * log2(e)), split hi/lo ----
    const float SCALE = 0.125f * 1.44269504088896340736f;
    uint32_t qh[4][4], ql[4][4];
    {
        const float* qp = q + ((size_t)b * CN + nt * 128 + wid * 16) * CC + h * CD;
        const float* qr0 = qp + (size_t)gid * CC;
        const float* qr1 = qp + (size_t)(gid + 8) * CC;
#pragma unroll
        for (int ks = 0; ks < 4; ks++) {
            int c = ks * 16 + 2 * tig;
            float2 x00 = *(const float2*)(qr0 + c);
            float2 x10 = *(const float2*)(qr1 + c);
            float2 x01 = *(const float2*)(qr0 + c + 8);
            float2 x11 = *(const float2*)(qr1 + c + 8);
            split2(x00.x * SCALE, x00.y * SCALE, qh[ks][0], ql[ks][0]);
            split2(x10.x * SCALE, x10.y * SCALE, qh[ks][1], ql[ks][1]);
            split2(x01.x * SCALE, x01.y * SCALE, qh[ks][2], ql[ks][2]);
            split2(x11.x * SCALE, x11.y * SCALE, qh[ks][3], ql[ks][3]);
        }
    }

    float o[8][4];
#pragma unroll
    for (int j = 0; j < 8; j++)
#pragma unroll
        for (int qi = 0; qi < 4; qi++) o[j][qi] = 0.f;
    float m0 = -1e30f, m1 = -1e30f, l0 = 0.f, l1 = 0.f;

    const int nblocks = CM / 64;    // 32
    for (int jt = 0; jt < nblocks; jt++) {
        int buf = jt & 1;
        if (jt + 1 < nblocks) issue(jt + 1, buf ^ 1);
        cp_commit();
        cp_wait1();
        __syncthreads();

        const uint32_t* Kh = fsm + buf * FBUF;
        const uint32_t* Kl = Kh + FT;
        const uint32_t* Vh = Kh + 2 * FT;
        const uint32_t* Vl = Kh + 3 * FT;

        // ---- S = Q K^T (3-term split) ----
        float s[8][4];
#pragma unroll
        for (int j = 0; j < 8; j++)
#pragma unroll
            for (int qi = 0; qi < 4; qi++) s[j][qi] = 0.f;

#pragma unroll
        for (int ks = 0; ks < 4; ks++) {
            const int ac = tig + ks * 8;
#pragma unroll
            for (int j = 0; j < 8; j++) {
                const int br = j * 8 + gid;
                uint32_t kh0 = Kh[br * 36 + ac], kh1 = Kh[br * 36 + ac + 4];
                uint32_t kl0 = Kl[br * 36 + ac], kl1 = Kl[br * 36 + ac + 4];
                mma16816(s[j], qh[ks][0], qh[ks][1], qh[ks][2], qh[ks][3], kh0, kh1);
                mma16816(s[j], qh[ks][0], qh[ks][1], qh[ks][2], qh[ks][3], kl0, kl1);
                mma16816(s[j], ql[ks][0], ql[ks][1], ql[ks][2], ql[ks][3], kh0, kh1);
            }
        }

        // ---- online softmax (rows gid, gid+8; base-2 domain) ----
        float mb0 = -1e30f, mb1 = -1e30f;
#pragma unroll
        for (int j = 0; j < 8; j++) {
            mb0 = fmaxf(mb0, fmaxf(s[j][0], s[j][1]));
            mb1 = fmaxf(mb1, fmaxf(s[j][2], s[j][3]));
        }
        mb0 = fmaxf(mb0, __shfl_xor_sync(0xffffffffu, mb0, 1));
        mb0 = fmaxf(mb0, __shfl_xor_sync(0xffffffffu, mb0, 2));
        mb1 = fmaxf(mb1, __shfl_xor_sync(0xffffffffu, mb1, 1));
        mb1 = fmaxf(mb1, __shfl_xor_sync(0xffffffffu, mb1, 2));

        float mn0 = fmaxf(m0, mb0), mn1 = fmaxf(m1, mb1);
        float al0 = exp2f(m0 - mn0), al1 = exp2f(m1 - mn1);
        m0 = mn0; m1 = mn1;

        float rs0 = 0.f, rs1 = 0.f;
#pragma unroll
        for (int j = 0; j < 8; j++) {
            s[j][0] = exp2f(s[j][0] - mn0);
            s[j][1] = exp2f(s[j][1] - mn0);
            s[j][2] = exp2f(s[j][2] - mn1);
            s[j][3] = exp2f(s[j][3] - mn1);
            rs0 += s[j][0] + s[j][1];
            rs1 += s[j][2] + s[j][3];
        }
        rs0 += __shfl_xor_sync(0xffffffffu, rs0, 1);
        rs0 += __shfl_xor_sync(0xffffffffu, rs0, 2);
        rs1 += __shfl_xor_sync(0xffffffffu, rs1, 1);
        rs1 += __shfl_xor_sync(0xffffffffu, rs1, 2);
        l0 = l0 * al0 + rs0;
        l1 = l1 * al1 + rs1;

#pragma unroll
        for (int j = 0; j < 8; j++) {
            o[j][0] *= al0; o[j][1] *= al0;
            o[j][2] *= al1; o[j][3] *= al1;
        }

        // ---- O += P V (3-term split) ----
#pragma unroll
        for (int jc = 0; jc < 4; jc++) {
            uint32_t ph[4], pl[4];
            split2(s[2*jc][0],   s[2*jc][1],   ph[0], pl[0]);
            split2(s[2*jc][2],   s[2*jc][3],   ph[1], pl[1]);
            split2(s[2*jc+1][0], s[2*jc+1][1], ph[2], pl[2]);
            split2(s[2*jc+1][2], s[2*jc+1][3], ph[3], pl[3]);
            const int ac = tig + jc * 8;
#pragma unroll
            for (int jf = 0; jf < 8; jf++) {
                const int br = jf * 8 + gid;
                uint32_t vh0 = Vh[br * 36 + ac], vh1 = Vh[br * 36 + ac + 4];
                uint32_t vl0 = Vl[br * 36 + ac], vl1 = Vl[br * 36 + ac + 4];
                mma16816(o[jf], ph[0], ph[1], ph[2], ph[3], vh0, vh1);
                mma16816(o[jf], ph[0], ph[1], ph[2], ph[3], vl0, vl1);
                mma16816(o[jf], pl[0], pl[1], pl[2], pl[3], vh0, vh1);
            }
        }
        __syncthreads();
    }

    // ---- epilogue ----
    float inv0 = 1.f / l0, inv1 = 1.f / l1;
    {
        int r0 = nt * 128 + wid * 16 + gid;
        float* ob0 = outp + ((size_t)b * CN + r0) * CC + h * CD;
        float* ob1 = ob0 + 8 * CC;
#pragma unroll
        for (int jf = 0; jf < 8; jf++) {
            int col = jf * 8 + 2 * tig;
            float2 w0, w1;
            w0.x = o[jf][0] * inv0; w0.y = o[jf][1] * inv0;
            w1.x = o[jf][2] * inv1; w1.y = o[jf][3] * inv1;
            *(float2*)(ob0 + col) = w0;
            *(float2*)(ob1 + col) = w1;
        }
    }
}

// ----------------------------------------------------------------------------
// Launch
// ----------------------------------------------------------------------------
extern "C" void kernel_launch(void* const* d_in, const int* in_sizes, int n_in,
                              void* d_out, int out_size)
{
    const float* x     = (const float*)d_in[0];
    const float* ctx   = (const float*)d_in[1];
    const float* fc    = (const float*)d_in[2];
    const float* Wq    = (const float*)d_in[3];
    const float* Wkv   = (const float*)d_in[4];
    const float* Wproj = (const float*)d_in[5];
    const float* bproj = (const float*)d_in[6];
    float* out = (float*)d_out;

    float *q, *kvp, *attn;
    cudaGetSymbolAddress((void**)&q,    g_q);
    cudaGetSymbolAddress((void**)&kvp,  g_kv);
    cudaGetSymbolAddress((void**)&attn, g_attn);

    cudaFuncSetAttribute(flash_mma_kernel,
                         cudaFuncAttributeMaxDynamicSharedMemorySize, FLASH_SMEM);

    // 1) q = x @ Wq^T
    gemm_mma_kernel<<<dim3(CC / 128, (CB * CN) / 128), 256>>>(
        x, Wq, q, CB * CN, CC, CC, nullptr);

    // 2) kv = context @ Wkv^T
    gemm_mma_kernel<<<dim3((2 * CC) / 128, (CB * CM) / 128), 256>>>(
        ctx, Wkv, kvp, CB * CM, 2 * CC, CC, nullptr);

    // 3) RoPE on q (k rope folded into conv pre-pass)
    rope_kernel<<<(CB * CN * 512 + 255) / 256, 256>>>(q, fc, CB * CN, CC);

    // 4) convert pre-pass: k rope+split, v split+transpose
    conv_kernel<<<dim3(CM / 64, CH, CB), 256>>>(fc);

    // 5) tensor-core flash attention
    flash_mma_kernel<<<dim3(CN / 128, CH, CB), 256, FLASH_SMEM>>>(q, attn);

    // 6) out = attn @ Wproj^T + bproj
    gemm_mma_kernel<<<dim3(CC / 128, (CB * CN) / 128), 256>>>(
        attn, Wproj, out, CB * CN, CC, CC, bproj);
}